// round 14
// baseline (speedup 1.0000x reference)
#include <cuda_runtime.h>

// Problem constants: K=2 speakers, M=2 masks, T=3000, F=513, D=6
#define KF   513
#define TT   3000
#define TFE  (TT*KF)          // 1,539,000
#define NCHUNK 75
#define CHUNK  (TT/NCHUNK)    // 40
#define T_TILE 8              // apply: t-rows per block

#define GPART_N (NCHUNK*4*42*KF)   // 6,463,800 floats (25.9 MB)
#define GPSD_N  (4*KF*72)          // 147,744 floats
#define GW_N    (2*KF*12)          // 12,312 floats

__device__ float g_part[GPART_N];
__device__ float g_psd[GPSD_N];
__device__ float g_w[GW_N];

// ---------------------------------------------------------------------------
// Kernel 1 (CROSS-FACTORED, smem-free): one thread owns one f and ALL 4 km.
// Per t: compute the 36 km-independent Hermitian cross terms ONCE, then one
// FMA per (km, term). 216 inst/(t,f) vs 336 before (-36% FMA). Every input
// element is read by exactly one thread -> no smem, no syncs, pure streaming.
// ---------------------------------------------------------------------------
__global__ __launch_bounds__(128) void psd_partial_kernel(
    const float* __restrict__ masks,
    const float* __restrict__ Or,
    const float* __restrict__ Oi)
{
    int f  = blockIdx.x * 128 + threadIdx.x;
    int fc = f < KF ? f : KF - 1;      // clamp for edge-tile loads
    int c  = blockIdx.y;               // t-chunk

    float accR[4][21];
    float accI[4][15];
#pragma unroll
    for (int km = 0; km < 4; km++) {
#pragma unroll
        for (int p = 0; p < 21; p++) accR[km][p] = 0.f;
#pragma unroll
        for (int q = 0; q < 15; q++) accI[km][q] = 0.f;
    }

    int base = c * CHUNK * KF + fc;

#pragma unroll 2
    for (int t = 0; t < CHUNK; t++) {
        int off = base + t * KF;
        float mk0 = masks[0 * TFE + off];
        float mk1 = masks[1 * TFE + off];
        float mk2 = masks[2 * TFE + off];
        float mk3 = masks[3 * TFE + off];
        float vr[6], vi[6];
#pragma unroll
        for (int d = 0; d < 6; d++) {
            vr[d] = Or[d * TFE + off];
            vi[d] = Oi[d * TFE + off];
        }
        int p = 0, q = 0;
#pragma unroll
        for (int d = 0; d < 6; d++) {
#pragma unroll
            for (int D = d; D < 6; D++) {
                float cr = fmaf(vr[d], vr[D], vi[d] * vi[D]);   // Re(v_d conj(v_D))
                accR[0][p] = fmaf(mk0, cr, accR[0][p]);
                accR[1][p] = fmaf(mk1, cr, accR[1][p]);
                accR[2][p] = fmaf(mk2, cr, accR[2][p]);
                accR[3][p] = fmaf(mk3, cr, accR[3][p]);
                if (D != d) {
                    float ci = fmaf(vi[d], vr[D], -vr[d] * vi[D]); // Im(v_d conj(v_D))
                    accI[0][q] = fmaf(mk0, ci, accI[0][q]);
                    accI[1][q] = fmaf(mk1, ci, accI[1][q]);
                    accI[2][q] = fmaf(mk2, ci, accI[2][q]);
                    accI[3][q] = fmaf(mk3, ci, accI[3][q]);
                    q++;
                }
                p++;
            }
        }
    }

    if (f < KF) {
#pragma unroll
        for (int km = 0; km < 4; km++) {
            int ob = (c * 4 + km) * 42 * KF + f;
            int p = 0, q = 0;
#pragma unroll
            for (int d = 0; d < 6; d++) {
#pragma unroll
                for (int D = d; D < 6; D++) {
                    g_part[ob + (2 * p) * KF]     = accR[km][p];
                    g_part[ob + (2 * p + 1) * KF] = (D != d) ? accI[km][q] : 0.f;
                    if (D != d) q++;
                    p++;
                }
            }
        }
    }
}

// ---------------------------------------------------------------------------
// Kernel 2: deterministic ordered reduction over chunks; expand Hermitian.
// ---------------------------------------------------------------------------
__global__ __launch_bounds__(128) void psd_reduce_kernel()
{
    int f = blockIdx.y * 128 + threadIdx.x;
    if (f >= KF) return;
    int kmj = blockIdx.x;                 // 0..167
    int km  = kmj / 42;
    int j   = kmj - km * 42;

    float s = 0.f;
    for (int cc = 0; cc < NCHUNK; cc++)
        s += g_part[((cc * 4 + km) * 42 + j) * KF + f];

    int p  = j >> 1;
    int ri = j & 1;
    int d = 0, q = p;                     // upper-tri pair p -> (d,D)
    while (q >= 6 - d) { q -= 6 - d; d++; }
    int D = d + q;

    int base = (km * KF + f) * 72;
    g_psd[base + (d * 6 + D) * 2 + ri] = s;
    if (d != D)
        g_psd[base + (D * 6 + d) * 2 + ri] = ri ? -s : s;   // Hermitian mirror
}

// ---------------------------------------------------------------------------
// Kernel 3: stack-free warp-parallel fp32 Gauss-Jordan in shared memory.
// ---------------------------------------------------------------------------
__global__ __launch_bounds__(128) void solve_kernel_ws()
{
    __shared__ float sAr[4][36], sAi[4][36], sBr[4][36], sBi[4][36];
    int w    = threadIdx.x >> 5;
    int lane = threadIdx.x & 31;
    int idx  = blockIdx.x * 4 + w;        // (k,f) system id
    if (idx >= 2 * KF) return;            // whole warp exits together
    int k = idx / KF;
    int f = idx - k * KF;

    int  l0 = lane;
    int  l1 = lane + 32;
    bool h1 = lane < 4;
    int  r0 = l0 / 6, e0 = l0 - 6 * r0;
    int  r1 = l1 / 6, e1 = l1 - 6 * r1;

    int aBase = ((k * 2 + 1) * KF + f) * 72;  // interference (m=1)
    int bBase = ((k * 2 + 0) * KF + f) * 72;  // target (m=0)
    sAr[w][l0] = g_psd[aBase + 2 * l0];
    sAi[w][l0] = g_psd[aBase + 2 * l0 + 1];
    sBr[w][l0] = g_psd[bBase + 2 * l0];
    sBi[w][l0] = g_psd[bBase + 2 * l0 + 1];
    if (h1) {
        sAr[w][l1] = g_psd[aBase + 2 * l1];
        sAi[w][l1] = g_psd[aBase + 2 * l1 + 1];
        sBr[w][l1] = g_psd[bBase + 2 * l1];
        sBi[w][l1] = g_psd[bBase + 2 * l1 + 1];
    }
    __syncwarp();

#pragma unroll
    for (int col = 0; col < 6; col++) {
        float pr  = sAr[w][col * 7], pi = sAi[w][col * 7];
        float inv = 1.f / (pr * pr + pi * pi);
        float srr =  pr * inv;
        float sii = -pi * inv;
        __syncwarp();
        if (r0 == col) {
            float ar = sAr[w][l0], ai = sAi[w][l0];
            sAr[w][l0] = ar * srr - ai * sii;
            sAi[w][l0] = ar * sii + ai * srr;
            float br = sBr[w][l0], bi = sBi[w][l0];
            sBr[w][l0] = br * srr - bi * sii;
            sBi[w][l0] = br * sii + bi * srr;
        }
        if (h1 && r1 == col) {
            float ar = sAr[w][l1], ai = sAi[w][l1];
            sAr[w][l1] = ar * srr - ai * sii;
            sAi[w][l1] = ar * sii + ai * srr;
            float br = sBr[w][l1], bi = sBi[w][l1];
            sBr[w][l1] = br * srr - bi * sii;
            sBi[w][l1] = br * sii + bi * srr;
        }
        __syncwarp();
        float f0r = 0.f, f0i = 0.f, p0r = 0.f, p0i = 0.f, q0r = 0.f, q0i = 0.f;
        if (r0 != col) {
            f0r = sAr[w][r0 * 6 + col];  f0i = sAi[w][r0 * 6 + col];
            p0r = sAr[w][col * 6 + e0];  p0i = sAi[w][col * 6 + e0];
            q0r = sBr[w][col * 6 + e0];  q0i = sBi[w][col * 6 + e0];
        }
        float f1r = 0.f, f1i = 0.f, p1r = 0.f, p1i = 0.f, q1r = 0.f, q1i = 0.f;
        if (h1 && r1 != col) {
            f1r = sAr[w][r1 * 6 + col];  f1i = sAi[w][r1 * 6 + col];
            p1r = sAr[w][col * 6 + e1];  p1i = sAi[w][col * 6 + e1];
            q1r = sBr[w][col * 6 + e1];  q1i = sBi[w][col * 6 + e1];
        }
        __syncwarp();
        if (r0 != col) {
            sAr[w][l0] -= f0r * p0r - f0i * p0i;
            sAi[w][l0] -= f0r * p0i + f0i * p0r;
            sBr[w][l0] -= f0r * q0r - f0i * q0i;
            sBi[w][l0] -= f0r * q0i + f0i * q0r;
        }
        if (h1 && r1 != col) {
            sAr[w][l1] -= f1r * p1r - f1i * p1i;
            sAi[w][l1] -= f1r * p1i + f1i * p1r;
            sBr[w][l1] -= f1r * q1r - f1i * q1i;
            sBi[w][l1] -= f1r * q1i + f1i * q1r;
        }
        __syncwarp();
    }

    float trr = sBr[w][0] + sBr[w][7] + sBr[w][14] +
                sBr[w][21] + sBr[w][28] + sBr[w][35];
    const float tinyf = 1.17549435e-38f;
    float lam  = trr < tinyf ? tinyf : trr;
    float invl = 1.f / lam;

    if (e0 == 0) {                        // lanes 0,6,12,18,24,30 own phi[r][0]
        int wB = (k * KF + f) * 12 + 2 * r0;
        g_w[wB]     =  sBr[w][l0] * invl;   // conj(beamformer)
        g_w[wB + 1] = -sBi[w][l0] * invl;
    }
}

// ---------------------------------------------------------------------------
// Kernel 4: enh real part, float32 [k,t,f]. Explicit register double-buffer:
// load t+1's 12 Obs values while computing t -> memory latency stays hidden
// without relying on the scheduler (R13 kept regs=32 and serialized).
// ---------------------------------------------------------------------------
__global__ __launch_bounds__(128) void apply_kernel(
    const float* __restrict__ Or,
    const float* __restrict__ Oi,
    float* __restrict__ out,
    int out_floats)
{
    int f  = blockIdx.x * 128 + threadIdx.x;
    int t0 = blockIdx.y * T_TILE;
    if (f >= KF) return;

    float w0r[6], w0i[6], w1r[6], w1i[6];
#pragma unroll
    for (int d = 0; d < 6; d++) {
        w0r[d] = g_w[(0 * KF + f) * 12 + 2 * d];
        w0i[d] = g_w[(0 * KF + f) * 12 + 2 * d + 1];
        w1r[d] = g_w[(1 * KF + f) * 12 + 2 * d];
        w1i[d] = g_w[(1 * KF + f) * 12 + 2 * d + 1];
    }

    int i0 = t0 * KF + f;
    float ar[6], ai[6], br[6], bi[6];
#pragma unroll
    for (int d = 0; d < 6; d++) {
        ar[d] = Or[d * TFE + i0];
        ai[d] = Oi[d * TFE + i0];
    }

#pragma unroll
    for (int tt = 0; tt < T_TILE; tt++) {
        int i = i0 + tt * KF;
        if (tt + 1 < T_TILE) {                 // prefetch next t into b-regs
            int i2 = i + KF;
#pragma unroll
            for (int d = 0; d < 6; d++) {
                br[d] = Or[d * TFE + i2];
                bi[d] = Oi[d * TFE + i2];
            }
        }
        float e0 = 0.f, e1 = 0.f;
#pragma unroll
        for (int d = 0; d < 6; d++) {
            e0 = fmaf(w0r[d], ar[d], fmaf(-w0i[d], ai[d], e0));
            e1 = fmaf(w1r[d], ar[d], fmaf(-w1i[d], ai[d], e1));
        }
        if (i < out_floats)       out[i]       = e0;
        if (TFE + i < out_floats) out[TFE + i] = e1;
        if (tt + 1 < T_TILE) {
#pragma unroll
            for (int d = 0; d < 6; d++) { ar[d] = br[d]; ai[d] = bi[d]; }
        }
    }
}

// ---------------------------------------------------------------------------
extern "C" void kernel_launch(void* const* d_in, const int* in_sizes, int n_in,
                              void* d_out, int out_size)
{
    const float* masks = 0;
    const float* Or    = 0;
    const float* Oi    = 0;
    for (int i = 0; i < n_in; i++) {
        int sz = in_sizes[i];
        if (sz == 4 * TFE) {
            masks = (const float*)d_in[i];
        } else if (sz == 6 * TFE) {
            if (!Or) Or = (const float*)d_in[i];
            else if (!Oi) Oi = (const float*)d_in[i];
        }
    }
    if (!masks || !Or || !Oi || !d_out) return;

    int out_floats = out_size;            // literal float32 element count

    dim3 g1((KF + 127) / 128, NCHUNK);
    psd_partial_kernel<<<g1, 128>>>(masks, Or, Oi);

    dim3 g2(4 * 42, (KF + 127) / 128);
    psd_reduce_kernel<<<g2, 128>>>();

    solve_kernel_ws<<<(2 * KF + 3) / 4, 128>>>();

    dim3 g4((KF + 127) / 128, TT / T_TILE);
    apply_kernel<<<g4, 128>>>(Or, Oi, (float*)d_out, out_floats);
}

// round 15
// speedup vs baseline: 1.2715x; 1.2715x over previous
#include <cuda_runtime.h>

// Problem constants: K=2 speakers, M=2 masks, T=3000, F=513, D=6
#define KF   513
#define TT   3000
#define TFE  (TT*KF)          // 1,539,000
#define NCHUNK 75
#define CHUNK  (TT/NCHUNK)    // 40
#define SLAB  4               // t-rows per pipeline stage
#define NSLAB (CHUNK/SLAB)    // 10
#define T_TILE 4              // apply: t-rows per block

#define GPART_N (NCHUNK*4*36*KF)   // 5,540,400 floats (22.2 MB): 36 components
#define GPSD_N  (4*KF*72)          // 147,744 floats
#define GW_N    (2*KF*12)          // 12,312 floats

__device__ float g_part[GPART_N];
__device__ float g_psd[GPSD_N];
__device__ float g_w[GW_N];

// ---- packed f32x2 helpers (Blackwell-native paired FP32) --------------------
typedef unsigned long long u64;
__device__ __forceinline__ u64 pk2(float lo, float hi) {
    u64 r; asm("mov.b64 %0,{%1,%2};" : "=l"(r) : "f"(lo), "f"(hi)); return r;
}
__device__ __forceinline__ void upk2(u64 v, float& lo, float& hi) {
    asm("mov.b64 {%0,%1},%2;" : "=f"(lo), "=f"(hi) : "l"(v));
}
__device__ __forceinline__ u64 fma2(u64 a, u64 b, u64 c) {
    u64 r; asm("fma.rn.f32x2 %0,%1,%2,%3;" : "=l"(r) : "l"(a), "l"(b), "l"(c)); return r;
}
__device__ __forceinline__ u64 mul2(u64 a, u64 b) {
    u64 r; asm("mul.rn.f32x2 %0,%1,%2;" : "=l"(r) : "l"(a), "l"(b)); return r;
}
#define SGNMASK 0x8000000080000000ULL

// ---------------------------------------------------------------------------
// Kernel 1: PSD partials. Warp-specialized over COMPONENTS: the 36 Hermitian
// cross terms (21 Re + 15 Im) are km-independent; warp w computes components
// [9w, 9w+9) ONCE and applies all 4 masks (acc[9][4] = 36 u64 per thread).
// Two t-steps processed per iteration packed in f32x2. Double-buffered smem.
// ---------------------------------------------------------------------------
__global__ __launch_bounds__(128) void psd_partial_kernel(
    const float* __restrict__ masks,
    const float* __restrict__ Or,
    const float* __restrict__ Oi)
{
    __shared__ float s_m [2][4][SLAB][32];
    __shared__ float s_or[2][6][SLAB][32];
    __shared__ float s_oi[2][6][SLAB][32];

    int tid  = threadIdx.x;
    int lane = tid & 31;
    int wid  = tid >> 5;               // warp id: loader t-row AND component group
    int f0   = blockIdx.x * 32;
    int f    = f0 + lane;
    int fc   = f < KF ? f : KF - 1;    // clamp for edge tile loads
    int c    = blockIdx.y;             // t-chunk

    int base = wid * KF + fc;          // loader: addr = plane*TFE + base + tg*KF

    u64 acc[9][4];
#pragma unroll
    for (int i = 0; i < 9; i++)
#pragma unroll
        for (int j = 0; j < 4; j++) acc[i][j] = 0ULL;

    float rm0, rm1, rm2, rm3;
    float ro0, ro1, ro2, ro3, ro4, ro5;
    float rj0, rj1, rj2, rj3, rj4, rj5;

#define ISSUE(S) do { int tg = (c * CHUNK + (S) * SLAB) * KF + base;          \
        rm0 = masks[0 * TFE + tg];  rm1 = masks[1 * TFE + tg];                \
        rm2 = masks[2 * TFE + tg];  rm3 = masks[3 * TFE + tg];                \
        ro0 = Or[0 * TFE + tg];  rj0 = Oi[0 * TFE + tg];                      \
        ro1 = Or[1 * TFE + tg];  rj1 = Oi[1 * TFE + tg];                      \
        ro2 = Or[2 * TFE + tg];  rj2 = Oi[2 * TFE + tg];                      \
        ro3 = Or[3 * TFE + tg];  rj3 = Oi[3 * TFE + tg];                      \
        ro4 = Or[4 * TFE + tg];  rj4 = Oi[4 * TFE + tg];                      \
        ro5 = Or[5 * TFE + tg];  rj5 = Oi[5 * TFE + tg];                      \
    } while (0)

#define COMMIT(B) do {                                                        \
        s_m [B][0][wid][lane] = rm0;  s_m [B][1][wid][lane] = rm1;            \
        s_m [B][2][wid][lane] = rm2;  s_m [B][3][wid][lane] = rm3;            \
        s_or[B][0][wid][lane] = ro0;  s_oi[B][0][wid][lane] = rj0;            \
        s_or[B][1][wid][lane] = ro1;  s_oi[B][1][wid][lane] = rj1;            \
        s_or[B][2][wid][lane] = ro2;  s_oi[B][2][wid][lane] = rj2;            \
        s_or[B][3][wid][lane] = ro3;  s_oi[B][3][wid][lane] = rj3;            \
        s_or[B][4][wid][lane] = ro4;  s_oi[B][4][wid][lane] = rj4;            \
        s_or[B][5][wid][lane] = ro5;  s_oi[B][5][wid][lane] = rj5;            \
    } while (0)

// cross terms of v_d * conj(v_D) on a packed t-pair
#define XR(d,D) fma2(vr[d], vr[D], mul2(vi[d], vi[D]))
#define XI(d,D) fma2(vi[d], vr[D], mul2(nvr[d], vi[D]))
// accumulate component slot i for all 4 masks
#define ACC(i, EXPR) do { u64 cx = (EXPR);                                    \
        acc[i][0] = fma2(mk0, cx, acc[i][0]);                                 \
        acc[i][1] = fma2(mk1, cx, acc[i][1]);                                 \
        acc[i][2] = fma2(mk2, cx, acc[i][2]);                                 \
        acc[i][3] = fma2(mk3, cx, acc[i][3]); } while (0)

    ISSUE(0);
    COMMIT(0);
    __syncthreads();

    for (int s = 0; s < NSLAB; s++) {
        if (s + 1 < NSLAB) ISSUE(s + 1);       // next slab's LDGs in flight
        int b = s & 1;
#pragma unroll
        for (int tt = 0; tt < SLAB; tt += 2) {
            u64 mk0 = pk2(s_m[b][0][tt][lane], s_m[b][0][tt + 1][lane]);
            u64 mk1 = pk2(s_m[b][1][tt][lane], s_m[b][1][tt + 1][lane]);
            u64 mk2 = pk2(s_m[b][2][tt][lane], s_m[b][2][tt + 1][lane]);
            u64 mk3 = pk2(s_m[b][3][tt][lane], s_m[b][3][tt + 1][lane]);
            u64 vr[6], vi[6], nvr[6];
#pragma unroll
            for (int d = 0; d < 6; d++) {
                vr[d]  = pk2(s_or[b][d][tt][lane], s_or[b][d][tt + 1][lane]);
                vi[d]  = pk2(s_oi[b][d][tt][lane], s_oi[b][d][tt + 1][lane]);
                nvr[d] = vr[d] ^ SGNMASK;
            }
            switch (wid) {
            case 0:   // components 0-8: R(0,0..5), R(1,1..3)
                ACC(0, XR(0,0)); ACC(1, XR(0,1)); ACC(2, XR(0,2));
                ACC(3, XR(0,3)); ACC(4, XR(0,4)); ACC(5, XR(0,5));
                ACC(6, XR(1,1)); ACC(7, XR(1,2)); ACC(8, XR(1,3));
                break;
            case 1:   // components 9-17: R(1,4),R(1,5),R(2,2..5),R(3,3..5)
                ACC(0, XR(1,4)); ACC(1, XR(1,5)); ACC(2, XR(2,2));
                ACC(3, XR(2,3)); ACC(4, XR(2,4)); ACC(5, XR(2,5));
                ACC(6, XR(3,3)); ACC(7, XR(3,4)); ACC(8, XR(3,5));
                break;
            case 2:   // components 18-26: R(4,4),R(4,5),R(5,5),I(0,1..5),I(1,2)
                ACC(0, XR(4,4)); ACC(1, XR(4,5)); ACC(2, XR(5,5));
                ACC(3, XI(0,1)); ACC(4, XI(0,2)); ACC(5, XI(0,3));
                ACC(6, XI(0,4)); ACC(7, XI(0,5)); ACC(8, XI(1,2));
                break;
            default:  // components 27-35: I(1,3..5),I(2,3..5),I(3,4),I(3,5),I(4,5)
                ACC(0, XI(1,3)); ACC(1, XI(1,4)); ACC(2, XI(1,5));
                ACC(3, XI(2,3)); ACC(4, XI(2,4)); ACC(5, XI(2,5));
                ACC(6, XI(3,4)); ACC(7, XI(3,5)); ACC(8, XI(4,5));
                break;
            }
        }
        if (s + 1 < NSLAB) COMMIT((s + 1) & 1);
        __syncthreads();
    }
#undef ISSUE
#undef COMMIT
#undef XR
#undef XI
#undef ACC

    if (f < KF) {
#pragma unroll
        for (int i = 0; i < 9; i++) {
            int comp = wid * 9 + i;           // component id 0..35
#pragma unroll
            for (int km = 0; km < 4; km++) {
                float lo, hi;
                upk2(acc[i][km], lo, hi);
                g_part[((c * 4 + km) * 36 + comp) * KF + f] = lo + hi;
            }
        }
    }
}

// ---------------------------------------------------------------------------
// Kernel 2: deterministic reduction over chunks from the 36-component layout;
// expand to full Hermitian 6x6 (diag imag written as exact 0).
// ---------------------------------------------------------------------------
__global__ __launch_bounds__(128) void psd_reduce_kernel()
{
    int f = blockIdx.y * 128 + threadIdx.x;
    if (f >= KF) return;
    int kmj = blockIdx.x;                 // 0..167
    int km  = kmj / 42;
    int j   = kmj - km * 42;

    int p  = j >> 1;
    int ri = j & 1;
    int d = 0, q = p;                     // upper-tri pair p -> (d,D)
    while (q >= 6 - d) { q -= 6 - d; d++; }
    int D = d + q;

    int base = (km * KF + f) * 72;
    if (ri == 1 && d == D) {              // diagonal imaginary part == 0
        g_psd[base + (d * 6 + D) * 2 + 1] = 0.f;
        return;
    }
    int comp = (ri == 0) ? p : 21 + (p - (d + 1));   // component index 0..35

    float s = 0.f;
    for (int cc = 0; cc < NCHUNK; cc++)
        s += g_part[((cc * 4 + km) * 36 + comp) * KF + f];

    g_psd[base + (d * 6 + D) * 2 + ri] = s;
    if (d != D)
        g_psd[base + (D * 6 + d) * 2 + ri] = ri ? -s : s;   // Hermitian mirror
}

// ---------------------------------------------------------------------------
// Kernel 3: stack-free warp-parallel fp32 Gauss-Jordan in shared memory.
// ---------------------------------------------------------------------------
__global__ __launch_bounds__(128) void solve_kernel_ws()
{
    __shared__ float sAr[4][36], sAi[4][36], sBr[4][36], sBi[4][36];
    int w    = threadIdx.x >> 5;
    int lane = threadIdx.x & 31;
    int idx  = blockIdx.x * 4 + w;        // (k,f) system id
    if (idx >= 2 * KF) return;            // whole warp exits together
    int k = idx / KF;
    int f = idx - k * KF;

    int  l0 = lane;
    int  l1 = lane + 32;
    bool h1 = lane < 4;
    int  r0 = l0 / 6, e0 = l0 - 6 * r0;
    int  r1 = l1 / 6, e1 = l1 - 6 * r1;

    int aBase = ((k * 2 + 1) * KF + f) * 72;  // interference (m=1)
    int bBase = ((k * 2 + 0) * KF + f) * 72;  // target (m=0)
    sAr[w][l0] = g_psd[aBase + 2 * l0];
    sAi[w][l0] = g_psd[aBase + 2 * l0 + 1];
    sBr[w][l0] = g_psd[bBase + 2 * l0];
    sBi[w][l0] = g_psd[bBase + 2 * l0 + 1];
    if (h1) {
        sAr[w][l1] = g_psd[aBase + 2 * l1];
        sAi[w][l1] = g_psd[aBase + 2 * l1 + 1];
        sBr[w][l1] = g_psd[bBase + 2 * l1];
        sBi[w][l1] = g_psd[bBase + 2 * l1 + 1];
    }
    __syncwarp();

#pragma unroll
    for (int col = 0; col < 6; col++) {
        float pr  = sAr[w][col * 7], pi = sAi[w][col * 7];
        float inv = 1.f / (pr * pr + pi * pi);
        float srr =  pr * inv;
        float sii = -pi * inv;
        __syncwarp();
        if (r0 == col) {
            float ar = sAr[w][l0], ai = sAi[w][l0];
            sAr[w][l0] = ar * srr - ai * sii;
            sAi[w][l0] = ar * sii + ai * srr;
            float br = sBr[w][l0], bi = sBi[w][l0];
            sBr[w][l0] = br * srr - bi * sii;
            sBi[w][l0] = br * sii + bi * srr;
        }
        if (h1 && r1 == col) {
            float ar = sAr[w][l1], ai = sAi[w][l1];
            sAr[w][l1] = ar * srr - ai * sii;
            sAi[w][l1] = ar * sii + ai * srr;
            float br = sBr[w][l1], bi = sBi[w][l1];
            sBr[w][l1] = br * srr - bi * sii;
            sBi[w][l1] = br * sii + bi * srr;
        }
        __syncwarp();
        float f0r = 0.f, f0i = 0.f, p0r = 0.f, p0i = 0.f, q0r = 0.f, q0i = 0.f;
        if (r0 != col) {
            f0r = sAr[w][r0 * 6 + col];  f0i = sAi[w][r0 * 6 + col];
            p0r = sAr[w][col * 6 + e0];  p0i = sAi[w][col * 6 + e0];
            q0r = sBr[w][col * 6 + e0];  q0i = sBi[w][col * 6 + e0];
        }
        float f1r = 0.f, f1i = 0.f, p1r = 0.f, p1i = 0.f, q1r = 0.f, q1i = 0.f;
        if (h1 && r1 != col) {
            f1r = sAr[w][r1 * 6 + col];  f1i = sAi[w][r1 * 6 + col];
            p1r = sAr[w][col * 6 + e1];  p1i = sAi[w][col * 6 + e1];
            q1r = sBr[w][col * 6 + e1];  q1i = sBi[w][col * 6 + e1];
        }
        __syncwarp();
        if (r0 != col) {
            sAr[w][l0] -= f0r * p0r - f0i * p0i;
            sAi[w][l0] -= f0r * p0i + f0i * p0r;
            sBr[w][l0] -= f0r * q0r - f0i * q0i;
            sBi[w][l0] -= f0r * q0i + f0i * q0r;
        }
        if (h1 && r1 != col) {
            sAr[w][l1] -= f1r * p1r - f1i * p1i;
            sAi[w][l1] -= f1r * p1i + f1i * p1r;
            sBr[w][l1] -= f1r * q1r - f1i * q1i;
            sBi[w][l1] -= f1r * q1i + f1i * q1r;
        }
        __syncwarp();
    }

    float trr = sBr[w][0] + sBr[w][7] + sBr[w][14] +
                sBr[w][21] + sBr[w][28] + sBr[w][35];
    const float tinyf = 1.17549435e-38f;
    float lam  = trr < tinyf ? tinyf : trr;
    float invl = 1.f / lam;

    if (e0 == 0) {                        // lanes 0,6,12,18,24,30 own phi[r][0]
        int wB = (k * KF + f) * 12 + 2 * r0;
        g_w[wB]     =  sBr[w][l0] * invl;   // conj(beamformer)
        g_w[wB + 1] = -sBi[w][l0] * invl;
    }
}

// ---------------------------------------------------------------------------
// Kernel 4: enh real part, float32 [k,t,f]. R13 version verbatim (18.4us,
// occ 71% -- the R14 double-buffer variant regressed; reverted).
// ---------------------------------------------------------------------------
__global__ __launch_bounds__(128) void apply_kernel(
    const float* __restrict__ Or,
    const float* __restrict__ Oi,
    float* __restrict__ out,
    int out_floats)
{
    int f  = blockIdx.x * 128 + threadIdx.x;
    int t0 = blockIdx.y * T_TILE;
    if (f >= KF) return;

    float w0r[6], w0i[6], w1r[6], w1i[6];
#pragma unroll
    for (int d = 0; d < 6; d++) {
        w0r[d] = g_w[(0 * KF + f) * 12 + 2 * d];
        w0i[d] = g_w[(0 * KF + f) * 12 + 2 * d + 1];
        w1r[d] = g_w[(1 * KF + f) * 12 + 2 * d];
        w1i[d] = g_w[(1 * KF + f) * 12 + 2 * d + 1];
    }

#pragma unroll
    for (int tt = 0; tt < T_TILE; tt++) {
        int i = (t0 + tt) * KF + f;
        float vr[6], vi[6];
#pragma unroll
        for (int d = 0; d < 6; d++) {
            vr[d] = Or[d * TFE + i];
            vi[d] = Oi[d * TFE + i];
        }
        float e0 = 0.f, e1 = 0.f;
#pragma unroll
        for (int d = 0; d < 6; d++) {
            e0 = fmaf(w0r[d], vr[d], fmaf(-w0i[d], vi[d], e0));
            e1 = fmaf(w1r[d], vr[d], fmaf(-w1i[d], vi[d], e1));
        }
        if (i < out_floats)       out[i]       = e0;
        if (TFE + i < out_floats) out[TFE + i] = e1;
    }
}

// ---------------------------------------------------------------------------
extern "C" void kernel_launch(void* const* d_in, const int* in_sizes, int n_in,
                              void* d_out, int out_size)
{
    const float* masks = 0;
    const float* Or    = 0;
    const float* Oi    = 0;
    for (int i = 0; i < n_in; i++) {
        int sz = in_sizes[i];
        if (sz == 4 * TFE) {
            masks = (const float*)d_in[i];
        } else if (sz == 6 * TFE) {
            if (!Or) Or = (const float*)d_in[i];
            else if (!Oi) Oi = (const float*)d_in[i];
        }
    }
    if (!masks || !Or || !Oi || !d_out) return;

    int out_floats = out_size;            // literal float32 element count

    dim3 g1((KF + 31) / 32, NCHUNK);
    psd_partial_kernel<<<g1, 128>>>(masks, Or, Oi);

    dim3 g2(4 * 42, (KF + 127) / 128);
    psd_reduce_kernel<<<g2, 128>>>();

    solve_kernel_ws<<<(2 * KF + 3) / 4, 128>>>();

    dim3 g4((KF + 127) / 128, TT / T_TILE);
    apply_kernel<<<g4, 128>>>(Or, Oi, (float*)d_out, out_floats);
}

// round 17
// speedup vs baseline: 1.4397x; 1.1323x over previous
#include <cuda_runtime.h>

// Problem constants: K=2 speakers, M=2 masks, T=3000, F=513, D=6
#define KF   513
#define TT   3000
#define TFE  (TT*KF)          // 1,539,000
#define NCHUNK 25
#define CHUNK  (TT/NCHUNK)    // 120
#define SLAB  4               // t-rows per pipeline stage (2 t-pairs)
#define NSLAB (CHUNK/SLAB)    // 30
#define T_TILE 4              // apply: t-rows per block

#define GPART_N (NCHUNK*4*36*KF)   // 1,846,800 floats (7.4 MB): 36 components
#define GPSD_N  (4*KF*72)          // 147,744 floats
#define GW_N    (2*KF*12)          // 12,312 floats

__device__ float g_part[GPART_N];
__device__ float g_psd[GPSD_N];
__device__ float g_w[GW_N];

// ---- packed f32x2 helpers (Blackwell-native paired FP32) --------------------
typedef unsigned long long u64;
__device__ __forceinline__ void upk2(u64 v, float& lo, float& hi) {
    asm("mov.b64 {%0,%1},%2;" : "=f"(lo), "=f"(hi) : "l"(v));
}
__device__ __forceinline__ u64 fma2(u64 a, u64 b, u64 c) {
    u64 r; asm("fma.rn.f32x2 %0,%1,%2,%3;" : "=l"(r) : "l"(a), "l"(b), "l"(c)); return r;
}
__device__ __forceinline__ u64 mul2(u64 a, u64 b) {
    u64 r; asm("mul.rn.f32x2 %0,%1,%2;" : "=l"(r) : "l"(a), "l"(b)); return r;
}
#define SGNMASK 0x8000000080000000ULL

// ---------------------------------------------------------------------------
// Kernel 1: PSD partials. Component-warp-specialized + f32x2 t-pairs.
// smem staged in t-pair-interleaved float2 layout so every packed operand is
// ONE aligned LDS.64 (R15 spent half its instructions on scalar LDS +
// mov.b64 packing). 16 LDS.64 + 60 FMA2 per t-pair per warp.
// ---------------------------------------------------------------------------
__global__ __launch_bounds__(128) void psd_partial_kernel(
    const float* __restrict__ masks,
    const float* __restrict__ Or,
    const float* __restrict__ Oi)
{
    // [buf][plane][tpair][lane][t01]; planes: 0-3 masks, 4-9 Or, 10-15 Oi
    __shared__ __align__(16) float s_d[2][16][SLAB / 2][32][2];

    int tid  = threadIdx.x;
    int lane = tid & 31;
    int wid  = tid >> 5;               // warp id: loader t-row AND component group
    int f0   = blockIdx.x * 32;
    int f    = f0 + lane;
    int fc   = f < KF ? f : KF - 1;    // clamp for edge tile loads
    int c    = blockIdx.y;             // t-chunk

    int base = wid * KF + fc;          // loader: addr = plane*TFE + base + tg*KF
    int tp_w = wid >> 1;               // loader's t-pair row
    int t01  = wid & 1;                // loader's slot within the pair

    u64 acc[9][4];
#pragma unroll
    for (int i = 0; i < 9; i++)
#pragma unroll
        for (int j = 0; j < 4; j++) acc[i][j] = 0ULL;

    float rg[16];

#define ISSUE(S) do { int tg = (c * CHUNK + (S) * SLAB) * KF + base;          \
        rg[0]  = masks[0 * TFE + tg];  rg[1]  = masks[1 * TFE + tg];          \
        rg[2]  = masks[2 * TFE + tg];  rg[3]  = masks[3 * TFE + tg];          \
        rg[4]  = Or[0 * TFE + tg];     rg[5]  = Or[1 * TFE + tg];             \
        rg[6]  = Or[2 * TFE + tg];     rg[7]  = Or[3 * TFE + tg];             \
        rg[8]  = Or[4 * TFE + tg];     rg[9]  = Or[5 * TFE + tg];             \
        rg[10] = Oi[0 * TFE + tg];     rg[11] = Oi[1 * TFE + tg];             \
        rg[12] = Oi[2 * TFE + tg];     rg[13] = Oi[3 * TFE + tg];             \
        rg[14] = Oi[4 * TFE + tg];     rg[15] = Oi[5 * TFE + tg];             \
    } while (0)

#define COMMIT(B) do {                                                        \
        _Pragma("unroll")                                                     \
        for (int pl = 0; pl < 16; pl++)                                       \
            s_d[B][pl][tp_w][lane][t01] = rg[pl];                             \
    } while (0)

#define LD2(B, pl, tp) (*(const u64*)&s_d[B][pl][tp][lane][0])
#define XR(d,D) fma2(vr[d], vr[D], mul2(vi[d], vi[D]))
#define XI(d,D) fma2(vi[d], vr[D], mul2(nvr[d], vi[D]))
#define ACC(i, EXPR) do { u64 cx = (EXPR);                                    \
        acc[i][0] = fma2(mk0, cx, acc[i][0]);                                 \
        acc[i][1] = fma2(mk1, cx, acc[i][1]);                                 \
        acc[i][2] = fma2(mk2, cx, acc[i][2]);                                 \
        acc[i][3] = fma2(mk3, cx, acc[i][3]); } while (0)

    ISSUE(0);
    COMMIT(0);
    __syncthreads();

    for (int s = 0; s < NSLAB; s++) {
        if (s + 1 < NSLAB) ISSUE(s + 1);       // next slab's LDGs in flight
        int b = s & 1;
#pragma unroll
        for (int tp = 0; tp < SLAB / 2; tp++) {
            u64 mk0 = LD2(b, 0, tp);
            u64 mk1 = LD2(b, 1, tp);
            u64 mk2 = LD2(b, 2, tp);
            u64 mk3 = LD2(b, 3, tp);
            u64 vr[6], vi[6], nvr[6];
#pragma unroll
            for (int d = 0; d < 6; d++) {
                vr[d]  = LD2(b, 4 + d, tp);
                vi[d]  = LD2(b, 10 + d, tp);
                nvr[d] = vr[d] ^ SGNMASK;
            }
            switch (wid) {
            case 0:   // components 0-8: R(0,0..5), R(1,1..3)
                ACC(0, XR(0,0)); ACC(1, XR(0,1)); ACC(2, XR(0,2));
                ACC(3, XR(0,3)); ACC(4, XR(0,4)); ACC(5, XR(0,5));
                ACC(6, XR(1,1)); ACC(7, XR(1,2)); ACC(8, XR(1,3));
                break;
            case 1:   // components 9-17: R(1,4),R(1,5),R(2,2..5),R(3,3..5)
                ACC(0, XR(1,4)); ACC(1, XR(1,5)); ACC(2, XR(2,2));
                ACC(3, XR(2,3)); ACC(4, XR(2,4)); ACC(5, XR(2,5));
                ACC(6, XR(3,3)); ACC(7, XR(3,4)); ACC(8, XR(3,5));
                break;
            case 2:   // components 18-26: R(4,4),R(4,5),R(5,5),I(0,1..5),I(1,2)
                ACC(0, XR(4,4)); ACC(1, XR(4,5)); ACC(2, XR(5,5));
                ACC(3, XI(0,1)); ACC(4, XI(0,2)); ACC(5, XI(0,3));
                ACC(6, XI(0,4)); ACC(7, XI(0,5)); ACC(8, XI(1,2));
                break;
            default:  // components 27-35: I(1,3..5),I(2,3..5),I(3,4),I(3,5),I(4,5)
                ACC(0, XI(1,3)); ACC(1, XI(1,4)); ACC(2, XI(1,5));
                ACC(3, XI(2,3)); ACC(4, XI(2,4)); ACC(5, XI(2,5));
                ACC(6, XI(3,4)); ACC(7, XI(3,5)); ACC(8, XI(4,5));
                break;
            }
        }
        if (s + 1 < NSLAB) COMMIT((s + 1) & 1);
        __syncthreads();
    }
#undef ISSUE
#undef COMMIT
#undef LD2
#undef XR
#undef XI
#undef ACC

    if (f < KF) {
#pragma unroll
        for (int i = 0; i < 9; i++) {
            int comp = wid * 9 + i;           // component id 0..35
#pragma unroll
            for (int km = 0; km < 4; km++) {
                float lo, hi;
                upk2(acc[i][km], lo, hi);
                g_part[((c * 4 + km) * 36 + comp) * KF + f] = lo + hi;
            }
        }
    }
}

// ---------------------------------------------------------------------------
// Kernel 2: deterministic reduction over chunks from the 36-component layout;
// expand to full Hermitian 6x6 (diag imag written as exact 0).
// ---------------------------------------------------------------------------
__global__ __launch_bounds__(128) void psd_reduce_kernel()
{
    int f = blockIdx.y * 128 + threadIdx.x;
    if (f >= KF) return;
    int kmj = blockIdx.x;                 // 0..167
    int km  = kmj / 42;
    int j   = kmj - km * 42;

    int p  = j >> 1;
    int ri = j & 1;
    int d = 0, q = p;                     // upper-tri pair p -> (d,D)
    while (q >= 6 - d) { q -= 6 - d; d++; }
    int D = d + q;

    int base = (km * KF + f) * 72;
    if (ri == 1 && d == D) {              // diagonal imaginary part == 0
        g_psd[base + (d * 6 + D) * 2 + 1] = 0.f;
        return;
    }
    int comp = (ri == 0) ? p : 21 + (p - (d + 1));   // component index 0..35

    float s = 0.f;
    for (int cc = 0; cc < NCHUNK; cc++)
        s += g_part[((cc * 4 + km) * 36 + comp) * KF + f];

    g_psd[base + (d * 6 + D) * 2 + ri] = s;
    if (d != D)
        g_psd[base + (D * 6 + d) * 2 + ri] = ri ? -s : s;   // Hermitian mirror
}

// ---------------------------------------------------------------------------
// Kernel 3: stack-free warp-parallel fp32 Gauss-Jordan in shared memory.
// ---------------------------------------------------------------------------
__global__ __launch_bounds__(128) void solve_kernel_ws()
{
    __shared__ float sAr[4][36], sAi[4][36], sBr[4][36], sBi[4][36];
    int w    = threadIdx.x >> 5;
    int lane = threadIdx.x & 31;
    int idx  = blockIdx.x * 4 + w;        // (k,f) system id
    if (idx >= 2 * KF) return;            // whole warp exits together
    int k = idx / KF;
    int f = idx - k * KF;

    int  l0 = lane;
    int  l1 = lane + 32;
    bool h1 = lane < 4;
    int  r0 = l0 / 6, e0 = l0 - 6 * r0;
    int  r1 = l1 / 6, e1 = l1 - 6 * r1;

    int aBase = ((k * 2 + 1) * KF + f) * 72;  // interference (m=1)
    int bBase = ((k * 2 + 0) * KF + f) * 72;  // target (m=0)
    sAr[w][l0] = g_psd[aBase + 2 * l0];
    sAi[w][l0] = g_psd[aBase + 2 * l0 + 1];
    sBr[w][l0] = g_psd[bBase + 2 * l0];
    sBi[w][l0] = g_psd[bBase + 2 * l0 + 1];
    if (h1) {
        sAr[w][l1] = g_psd[aBase + 2 * l1];
        sAi[w][l1] = g_psd[aBase + 2 * l1 + 1];
        sBr[w][l1] = g_psd[bBase + 2 * l1];
        sBi[w][l1] = g_psd[bBase + 2 * l1 + 1];
    }
    __syncwarp();

#pragma unroll
    for (int col = 0; col < 6; col++) {
        float pr  = sAr[w][col * 7], pi = sAi[w][col * 7];
        float inv = 1.f / (pr * pr + pi * pi);
        float srr =  pr * inv;
        float sii = -pi * inv;
        __syncwarp();
        if (r0 == col) {
            float ar = sAr[w][l0], ai = sAi[w][l0];
            sAr[w][l0] = ar * srr - ai * sii;
            sAi[w][l0] = ar * sii + ai * srr;
            float br = sBr[w][l0], bi = sBi[w][l0];
            sBr[w][l0] = br * srr - bi * sii;
            sBi[w][l0] = br * sii + bi * srr;
        }
        if (h1 && r1 == col) {
            float ar = sAr[w][l1], ai = sAi[w][l1];
            sAr[w][l1] = ar * srr - ai * sii;
            sAi[w][l1] = ar * sii + ai * srr;
            float br = sBr[w][l1], bi = sBi[w][l1];
            sBr[w][l1] = br * srr - bi * sii;
            sBi[w][l1] = br * sii + bi * srr;
        }
        __syncwarp();
        float f0r = 0.f, f0i = 0.f, p0r = 0.f, p0i = 0.f, q0r = 0.f, q0i = 0.f;
        if (r0 != col) {
            f0r = sAr[w][r0 * 6 + col];  f0i = sAi[w][r0 * 6 + col];
            p0r = sAr[w][col * 6 + e0];  p0i = sAi[w][col * 6 + e0];
            q0r = sBr[w][col * 6 + e0];  q0i = sBi[w][col * 6 + e0];
        }
        float f1r = 0.f, f1i = 0.f, p1r = 0.f, p1i = 0.f, q1r = 0.f, q1i = 0.f;
        if (h1 && r1 != col) {
            f1r = sAr[w][r1 * 6 + col];  f1i = sAi[w][r1 * 6 + col];
            p1r = sAr[w][col * 6 + e1];  p1i = sAi[w][col * 6 + e1];
            q1r = sBr[w][col * 6 + e1];  q1i = sBi[w][col * 6 + e1];
        }
        __syncwarp();
        if (r0 != col) {
            sAr[w][l0] -= f0r * p0r - f0i * p0i;
            sAi[w][l0] -= f0r * p0i + f0i * p0r;
            sBr[w][l0] -= f0r * q0r - f0i * q0i;
            sBi[w][l0] -= f0r * q0i + f0i * q0r;
        }
        if (h1 && r1 != col) {
            sAr[w][l1] -= f1r * p1r - f1i * p1i;
            sAi[w][l1] -= f1r * p1i + f1i * p1r;
            sBr[w][l1] -= f1r * q1r - f1i * q1i;
            sBi[w][l1] -= f1r * q1i + f1i * q1r;
        }
        __syncwarp();
    }

    float trr = sBr[w][0] + sBr[w][7] + sBr[w][14] +
                sBr[w][21] + sBr[w][28] + sBr[w][35];
    const float tinyf = 1.17549435e-38f;
    float lam  = trr < tinyf ? tinyf : trr;
    float invl = 1.f / lam;

    if (e0 == 0) {                        // lanes 0,6,12,18,24,30 own phi[r][0]
        int wB = (k * KF + f) * 12 + 2 * r0;
        g_w[wB]     =  sBr[w][l0] * invl;   // conj(beamformer)
        g_w[wB + 1] = -sBi[w][l0] * invl;
    }
}

// ---------------------------------------------------------------------------
// Kernel 4: enh real part, float32 [k,t,f]. R13/R15 version verbatim
// (18.4us standalone; expected to speed up from L2-resident Obs now that
// partials pressure dropped 22.2 -> 7.4 MB).
// ---------------------------------------------------------------------------
__global__ __launch_bounds__(128) void apply_kernel(
    const float* __restrict__ Or,
    const float* __restrict__ Oi,
    float* __restrict__ out,
    int out_floats)
{
    int f  = blockIdx.x * 128 + threadIdx.x;
    int t0 = blockIdx.y * T_TILE;
    if (f >= KF) return;

    float w0r[6], w0i[6], w1r[6], w1i[6];
#pragma unroll
    for (int d = 0; d < 6; d++) {
        w0r[d] = g_w[(0 * KF + f) * 12 + 2 * d];
        w0i[d] = g_w[(0 * KF + f) * 12 + 2 * d + 1];
        w1r[d] = g_w[(1 * KF + f) * 12 + 2 * d];
        w1i[d] = g_w[(1 * KF + f) * 12 + 2 * d + 1];
    }

#pragma unroll
    for (int tt = 0; tt < T_TILE; tt++) {
        int i = (t0 + tt) * KF + f;
        float vr[6], vi[6];
#pragma unroll
        for (int d = 0; d < 6; d++) {
            vr[d] = Or[d * TFE + i];
            vi[d] = Oi[d * TFE + i];
        }
        float e0 = 0.f, e1 = 0.f;
#pragma unroll
        for (int d = 0; d < 6; d++) {
            e0 = fmaf(w0r[d], vr[d], fmaf(-w0i[d], vi[d], e0));
            e1 = fmaf(w1r[d], vr[d], fmaf(-w1i[d], vi[d], e1));
        }
        if (i < out_floats)       out[i]       = e0;
        if (TFE + i < out_floats) out[TFE + i] = e1;
    }
}

// ---------------------------------------------------------------------------
extern "C" void kernel_launch(void* const* d_in, const int* in_sizes, int n_in,
                              void* d_out, int out_size)
{
    const float* masks = 0;
    const float* Or    = 0;
    const float* Oi    = 0;
    for (int i = 0; i < n_in; i++) {
        int sz = in_sizes[i];
        if (sz == 4 * TFE) {
            masks = (const float*)d_in[i];
        } else if (sz == 6 * TFE) {
            if (!Or) Or = (const float*)d_in[i];
            else if (!Oi) Oi = (const float*)d_in[i];
        }
    }
    if (!masks || !Or || !Oi || !d_out) return;

    int out_floats = out_size;            // literal float32 element count

    dim3 g1((KF + 31) / 32, NCHUNK);
    psd_partial_kernel<<<g1, 128>>>(masks, Or, Oi);

    dim3 g2(4 * 42, (KF + 127) / 128);
    psd_reduce_kernel<<<g2, 128>>>();

    solve_kernel_ws<<<(2 * KF + 3) / 4, 128>>>();

    dim3 g4((KF + 127) / 128, TT / T_TILE);
    apply_kernel<<<g4, 128>>>(Or, Oi, (float*)d_out, out_floats);
}